// round 9
// baseline (speedup 1.0000x reference)
#include <cuda_runtime.h>
#include <cuda_bf16.h>

// Single-pass fused blocked-scan RK4 on a 4-state LTI system, single-wave grid.
// x_{t+1} = Phi x_t + Gam u_t (exact RK4 algebra for linear ODE + ZOH input).
//   k_init : 16-thread double build of Phi, Gam, M[s]=Phi^(16*2^s), and the
//            phase-1 dot-product weights W[j] = Phi^(15-j) * Gam; zero flags.
//   k_main : <=148 co-resident blocks, 16 steps/thread:
//            phase1 = dot product b_p = sum_j W[j] u_j (no serial chain)
//            -> warp shuffle scan + warp-agg scan -> publish aggregate
//            -> one-warp decoupled lookback + 4-way fold -> per-thread start via
//            binary matrix powers -> phase2 STEP re-run (u re-read hits L2).

#define LSTEP 16
#define BLK 1024
#define MAXB 256

__device__ float g_fPhi[16];
__device__ float g_fGam[8];
__device__ float g_fM[18][16];        // M[s] = Phi^(LSTEP * 2^s)
__device__ float g_fW[LSTEP][8];      // W[j] = Phi^(15-j)*Gam, row-major 4x2
__device__ float4 g_agg[MAXB];
__device__ int g_flag[MAXB];

__global__ void k_init(const float* c, const float* m, const float* k,
                       const float* dtp) {
    __shared__ double sA[16], sP[16], sT[16], sR[16], sPhiD[16], sC[8];
    int t = threadIdx.x;           // 16 threads
    int r = t >> 2, col = t & 3;

    for (int i = t; i < MAXB; i += 16) g_flag[i] = 0;

    double c1 = c[0], c2 = c[1], c3 = c[2];
    double m1 = m[0], m2 = m[1];
    double k1 = k[0], k2 = k[1], k3 = k[2];
    double h = dtp[0];

    if (t == 0) {
        sA[0] = 0.0;  sA[1] = 1.0;  sA[2] = 0.0;  sA[3] = 0.0;
        sA[4] = -(k1 + k2) / m1; sA[5] = -(c1 + c2) / m1; sA[6] = k2 / m1; sA[7] = c2 / m1;
        sA[8] = 0.0;  sA[9] = 0.0;  sA[10] = 0.0; sA[11] = 1.0;
        sA[12] = k2 / m2; sA[13] = c2 / m2; sA[14] = -(k3 + k2) / m2; sA[15] = -(c3 + c2) / m2;
    }
    __syncwarp(0xffffu);

    double id = (r == col) ? 1.0 : 0.0;
    double h2 = h * h, h3 = h2 * h, h4 = h3 * h;
    double ph = id + h * sA[t];                 // Phi accumulator
    double g4 = h * id + (h2 / 2.0) * sA[t];    // G4 accumulator
    sP[t] = sA[t];
    __syncwarp(0xffffu);

    double coefP[3] = { h2 / 2.0, h3 / 6.0, h4 / 24.0 };
    double coefG[2] = { h3 / 6.0, h4 / 24.0 };
    for (int q = 0; q < 3; q++) {               // A^2, A^3, A^4
        double s = 0.0;
        for (int kk = 0; kk < 4; kk++) s += sP[r * 4 + kk] * sA[kk * 4 + col];
        __syncwarp(0xffffu);
        sP[t] = s;
        __syncwarp(0xffffu);
        ph += coefP[q] * s;
        if (q < 2) g4 += coefG[q] * s;
    }

    g_fPhi[t] = (float)ph;
    sT[t] = g4;
    sPhiD[t] = ph;
    __syncwarp(0xffffu);
    if (t < 8) {   // Gam = G4 * B with B[1][0]=1/m1, B[3][1]=1/m2
        int rr = t >> 1, cc = t & 1;
        double gv = sT[rr * 4 + (cc ? 3 : 1)] / (cc ? m2 : m1);
        g_fGam[t] = (float)gv;
        sC[t] = gv;                // C_15 = Gam
    }
    __syncwarp(0xffffu);

    // W[j] = Phi^(15-j) * Gam, built backwards: C_15 = Gam, C_{j-1} = Phi * C_j
    for (int j = LSTEP - 1; j >= 0; j--) {
        if (t < 8) g_fW[j][t] = (float)sC[t];
        __syncwarp(0xffffu);
        double nv = 0.0;
        if (t < 8) {
            int rr = t >> 1, cc = t & 1;
            for (int kk = 0; kk < 4; kk++) nv += sPhiD[rr * 4 + kk] * sC[kk * 2 + cc];
        }
        __syncwarp(0xffffu);
        if (t < 8) sC[t] = nv;
        __syncwarp(0xffffu);
    }

    // sR = Phi^LSTEP (LSTEP=16 -> 4 squarings of Phi)
    sR[t] = ph;
    __syncwarp(0xffffu);
    for (int q = 0; q < 4; q++) {
        double s = 0.0;
        for (int kk = 0; kk < 4; kk++) s += sR[r * 4 + kk] * sR[kk * 4 + col];
        __syncwarp(0xffffu);
        sR[t] = s;
        __syncwarp(0xffffu);
    }
    g_fM[0][t] = (float)sR[t];
    for (int ms = 1; ms < 18; ms++) {           // successive squarings
        double s = 0.0;
        for (int kk = 0; kk < 4; kk++) s += sR[r * 4 + kk] * sR[kk * 4 + col];
        __syncwarp(0xffffu);
        sR[t] = s;
        __syncwarp(0xffffu);
        g_fM[ms][t] = (float)sR[t];
    }
}

#define STEP(ua, ub)                                                                         \
    do {                                                                                     \
        float n0 = fmaf(P[3],  x3, fmaf(P[2],  x2, fmaf(P[1],  x1, fmaf(P[0],  x0,          \
                   fmaf(G[1], (ub), G[0] * (ua))))));                                        \
        float n1 = fmaf(P[7],  x3, fmaf(P[6],  x2, fmaf(P[5],  x1, fmaf(P[4],  x0,          \
                   fmaf(G[3], (ub), G[2] * (ua))))));                                        \
        float n2 = fmaf(P[11], x3, fmaf(P[10], x2, fmaf(P[9],  x1, fmaf(P[8],  x0,          \
                   fmaf(G[5], (ub), G[4] * (ua))))));                                        \
        float n3 = fmaf(P[15], x3, fmaf(P[14], x2, fmaf(P[13], x1, fmaf(P[12], x0,          \
                   fmaf(G[7], (ub), G[6] * (ua))))));                                        \
        x0 = n0; x1 = n1; x2 = n2; x3 = n3;                                                  \
    } while (0)

// _v = M*_w + _v
#define AFF(Mm, _v, _w)                                                                      \
    do {                                                                                     \
        float n0 = fmaf(Mm[0],  (_w).x, fmaf(Mm[1],  (_w).y, fmaf(Mm[2],  (_w).z, fmaf(Mm[3],  (_w).w, (_v).x)))); \
        float n1 = fmaf(Mm[4],  (_w).x, fmaf(Mm[5],  (_w).y, fmaf(Mm[6],  (_w).z, fmaf(Mm[7],  (_w).w, (_v).y)))); \
        float n2 = fmaf(Mm[8],  (_w).x, fmaf(Mm[9],  (_w).y, fmaf(Mm[10], (_w).z, fmaf(Mm[11], (_w).w, (_v).z)))); \
        float n3 = fmaf(Mm[12], (_w).x, fmaf(Mm[13], (_w).y, fmaf(Mm[14], (_w).z, fmaf(Mm[15], (_w).w, (_v).w)))); \
        (_v).x = n0; (_v).y = n1; (_v).z = n2; (_v).w = n3;                                  \
    } while (0)

// _w = M*_w
#define MATP(Mm, _w)                                                                         \
    do {                                                                                     \
        float n0 = fmaf(Mm[0],  (_w).x, fmaf(Mm[1],  (_w).y, fmaf(Mm[2],  (_w).z, Mm[3]  * (_w).w))); \
        float n1 = fmaf(Mm[4],  (_w).x, fmaf(Mm[5],  (_w).y, fmaf(Mm[6],  (_w).z, Mm[7]  * (_w).w))); \
        float n2 = fmaf(Mm[8],  (_w).x, fmaf(Mm[9],  (_w).y, fmaf(Mm[10], (_w).z, Mm[11] * (_w).w))); \
        float n3 = fmaf(Mm[12], (_w).x, fmaf(Mm[13], (_w).y, fmaf(Mm[14], (_w).z, Mm[15] * (_w).w))); \
        (_w).x = n0; (_w).y = n1; (_w).z = n2; (_w).w = n3;                                  \
    } while (0)

#define SHFL_UP4(_d, _v, _w)                                                                 \
    do {                                                                                     \
        (_w).x = __shfl_up_sync(0xffffffffu, (_v).x, (_d));                                  \
        (_w).y = __shfl_up_sync(0xffffffffu, (_v).y, (_d));                                  \
        (_w).z = __shfl_up_sync(0xffffffffu, (_v).z, (_d));                                  \
        (_w).w = __shfl_up_sync(0xffffffffu, (_v).w, (_d));                                  \
    } while (0)

__global__ void __launch_bounds__(BLK) k_main(const float* __restrict__ u,
                                              const float* __restrict__ x0in,
                                              float* __restrict__ out, int T) {
    __shared__ float sM[18][16];
    __shared__ float4 sW4[2 * LSTEP];      // W, float4-packed (rows 01 / rows 23 per step)
    __shared__ float4 sWagg[32];
    __shared__ float4 sWscan[32];
    __shared__ float4 sAgg[MAXB];
    __shared__ float4 sF[4];
    __shared__ int sLen[4];
    __shared__ float4 sPref;

    int tid = threadIdx.x;
    int lane = tid & 31, wrp = tid >> 5;
    int b = blockIdx.x;
    int p = b * BLK + tid;

    if (tid < 288) ((float*)sM)[tid] = ((const float*)g_fM)[tid];
    else if (tid >= 512 && tid < 512 + 8 * LSTEP)
        ((float*)sW4)[tid - 512] = ((const float*)g_fW)[tid - 512];

    float P[16], G[8];
#pragma unroll
    for (int i = 0; i < 16; i++) P[i] = g_fPhi[i];
#pragma unroll
    for (int i = 0; i < 8; i++) G[i] = g_fGam[i];
    __syncthreads();                               // sM, sW4 ready

    int t0 = p * LSTEP;
    int te = t0 + LSTEP; if (te > T) te = T;
    int rem = te - t0; if (rem < 0) rem = 0;       // steps this thread owns (0..16)

    const float4* u4 = (const float4*)(u + 2 * t0);

    // ---- phase 1: affine offset b_p as an ILP-4 dot product (no serial chain) ----
    float4 v = make_float4(0.f, 0.f, 0.f, 0.f);
    if (rem == LSTEP) {
        float4 A[LSTEP / 2];
#pragma unroll
        for (int j = 0; j < LSTEP / 2; j++) A[j] = u4[j];   // batched loads, MLP 8
        float e0 = 0.f, e1 = 0.f, e2 = 0.f, e3 = 0.f;
        float f0 = 0.f, f1 = 0.f, f2 = 0.f, f3 = 0.f;
#pragma unroll
        for (int j = 0; j < LSTEP / 2; j++) {
            float4 a = A[j];
            float4 ca0 = sW4[4 * j],     ca1 = sW4[4 * j + 1];   // W[2j]
            float4 cb0 = sW4[4 * j + 2], cb1 = sW4[4 * j + 3];   // W[2j+1]
            e0 = fmaf(ca0.x, a.x, fmaf(ca0.y, a.y, e0));
            e1 = fmaf(ca0.z, a.x, fmaf(ca0.w, a.y, e1));
            e2 = fmaf(ca1.x, a.x, fmaf(ca1.y, a.y, e2));
            e3 = fmaf(ca1.z, a.x, fmaf(ca1.w, a.y, e3));
            f0 = fmaf(cb0.x, a.z, fmaf(cb0.y, a.w, f0));
            f1 = fmaf(cb0.z, a.z, fmaf(cb0.w, a.w, f1));
            f2 = fmaf(cb1.x, a.z, fmaf(cb1.y, a.w, f2));
            f3 = fmaf(cb1.z, a.z, fmaf(cb1.w, a.w, f3));
        }
        v = make_float4(e0 + f0, e1 + f1, e2 + f2, e3 + f3);
        if (p == 0) {   // + Phi^16 * x0
            float4 xx = make_float4(x0in[0], x0in[1], x0in[2], x0in[3]);
            const float* M = sM[0];
            AFF(M, v, xx);
        }
    } else if (rem > 0) {
        float x0 = 0.f, x1 = 0.f, x2 = 0.f, x3 = 0.f;
        if (p == 0) { x0 = x0in[0]; x1 = x0in[1]; x2 = x0in[2]; x3 = x0in[3]; }
        int j = 0;
        for (; 2 * (j + 1) <= rem; j++) {
            float4 a = u4[j];
            STEP(a.x, a.y); STEP(a.z, a.w);
        }
        if (2 * j < rem) {
            float2 hh = *(const float2*)(u + 2 * (t0 + 2 * j));
            STEP(hh.x, hh.y);
        }
        v = make_float4(x0, x1, x2, x3);
    }

    // ---- warp Kogge-Stone scan (shuffles; M[0..4]) ----
#pragma unroll
    for (int s = 0; s < 5; s++) {
        int d = 1 << s;
        float4 w;
        SHFL_UP4(d, v, w);
        if (lane >= d) { const float* M = sM[s]; AFF(M, v, w); }
    }
    float4 ev;                                     // exclusive within-warp scan
    SHFL_UP4(1, v, ev);
    if (lane == 0) ev = make_float4(0.f, 0.f, 0.f, 0.f);
    if (lane == 31) sWagg[wrp] = v;
    __syncthreads();

    // ---- warp 0 scans the 32 warp aggregates (M[5..9]) ----
    if (wrp == 0) {
        float4 av = sWagg[lane];
#pragma unroll
        for (int s = 0; s < 5; s++) {
            int d = 1 << s;
            float4 w;
            SHFL_UP4(d, av, w);
            if (lane >= d) { const float* M = sM[5 + s]; AFF(M, av, w); }
        }
        sWscan[lane] = av;
    }
    __syncthreads();

    // ---- publish block aggregate ----
    if (tid == 0) {
        g_agg[b] = sWscan[31];
        __threadfence();
        atomicExch(&g_flag[b], 1);
    }

    // ---- decoupled lookback, ONE warp polls (lane-strided) ----
    if (wrp == 0) {
        for (int j = lane; j < b; j += 32) {
            while (atomicAdd(&g_flag[j], 0) == 0) { }
        }
        __threadfence();
        for (int j = lane; j < b; j += 32) sAgg[j] = g_agg[j];
    }
    __syncthreads();

    // ---- 4-way parallel fold: Pref_b = sum_{j<b} MB^{b-1-j} S_j, MB = M[10] ----
    const float* MB = sM[10];
    if (tid < 4) {
        int q = (b + 3) >> 2;
        int j0 = tid * q, j1 = j0 + q; if (j1 > b) j1 = b; if (j0 > b) j0 = b;
        float4 F = make_float4(0.f, 0.f, 0.f, 0.f);
        for (int j = j0; j < j1; j++) {
            float4 S = sAgg[j];
            MATP(MB, F);
            F.x += S.x; F.y += S.y; F.z += S.z; F.w += S.w;
        }
        sF[tid] = F; sLen[tid] = j1 - j0;
    }
    __syncthreads();
    if (tid == 0) {
        float4 acc = (b > 0) ? sF[0] : make_float4(0.f, 0.f, 0.f, 0.f);
#pragma unroll
        for (int l = 1; l < 4; l++) {
            int r = sLen[l];
#pragma unroll
            for (int s = 0; s < 7; s++)
                if ((r >> s) & 1) { const float* M = sM[10 + s]; MATP(M, acc); }
            float4 F = sF[l];
            acc.x += F.x; acc.y += F.y; acc.z += F.z; acc.w += F.w;
        }
        sPref = acc;
    }
    __syncthreads();

    if (t0 >= T) return;   // all barriers done; idle tail threads exit

    // ---- per-thread start:
    //      Phi^{16 tid} * Pref_b + Phi^{16 lane} * Wscan[wrp-1] + ev ----
    float x0, x1, x2, x3;
    if (p == 0) {
        x0 = x0in[0]; x1 = x0in[1]; x2 = x0in[2]; x3 = x0in[3];
    } else {
        float4 sv = make_float4(0.f, 0.f, 0.f, 0.f);
        if (b > 0) {
            sv = sPref;
#pragma unroll
            for (int s = 0; s < 10; s++)
                if ((tid >> s) & 1) { const float* M = sM[s]; MATP(M, sv); }
        }
        if (wrp > 0) {
            float4 wp = sWscan[wrp - 1];
#pragma unroll
            for (int s = 0; s < 5; s++)
                if ((lane >> s) & 1) { const float* M = sM[s]; MATP(M, wp); }
            sv.x += wp.x; sv.y += wp.y; sv.z += wp.z; sv.w += wp.w;
        }
        sv.x += ev.x; sv.y += ev.y; sv.z += ev.z; sv.w += ev.w;
        x0 = sv.x; x1 = sv.y; x2 = sv.z; x3 = sv.w;
    }

    // ---- phase 2: STEP re-run (u re-read: L2 hit), emit (z1, z2) per step ----
    if (rem == LSTEP) {
        float4* o4 = (float4*)(out + 2 * t0);
#pragma unroll
        for (int j = 0; j < LSTEP / 2; j++) {
            float4 a = u4[j];
            STEP(a.x, a.y); float p0 = x0, q0 = x2;
            STEP(a.z, a.w);
            o4[j] = make_float4(p0, q0, x0, x2);
        }
    } else {
        int j = 0;
        for (; 2 * (j + 1) <= rem; j++) {
            float4 a = u4[j];
            STEP(a.x, a.y); float p0 = x0, q0 = x2;
            STEP(a.z, a.w);
            *(float4*)(out + 2 * (t0 + 2 * j)) = make_float4(p0, q0, x0, x2);
        }
        if (2 * j < rem) {
            float2 hh = *(const float2*)(u + 2 * (t0 + 2 * j));
            STEP(hh.x, hh.y);
            *(float2*)(out + 2 * (t0 + 2 * j)) = make_float2(x0, x2);
        }
    }
}

extern "C" void kernel_launch(void* const* d_in, const int* in_sizes, int n_in,
                              void* d_out, int out_size) {
    const float* u  = (const float*)d_in[0];
    const float* x0 = (const float*)d_in[1];
    const float* c  = (const float*)d_in[2];
    const float* m  = (const float*)d_in[3];
    const float* k  = (const float*)d_in[4];
    const float* dt = (const float*)d_in[5];
    float* out = (float*)d_out;

    int T = in_sizes[0] / 2;
    int chains = (T + LSTEP - 1) / LSTEP;
    int grid = (chains + BLK - 1) / BLK;     // 123 for T = 2e6 -> single wave

    k_init<<<1, 16>>>(c, m, k, dt);
    k_main<<<grid, BLK>>>(u, x0, out, T);
}

// round 11
// speedup vs baseline: 1.0109x; 1.0109x over previous
#include <cuda_runtime.h>
#include <cuda_bf16.h>

// Single-pass fused blocked-scan RK4 on a 4-state LTI system, single-wave grid.
// x_{t+1} = Phi x_t + Gam u_t (exact RK4 algebra for linear ODE + ZOH input).
//   k_init : 16-thread double build of Phi, Gam, M[s]=Phi^(16*2^s) s=0..17,
//            R[j] = rows 0,2 of Phi^(j+1) (output-correction rows); zero flags.
//   k_main : <=148 co-resident blocks, 16 steps/thread:
//            phase1 STEP chain from 0, storing per-step (z1,z2) to smem
//            -> warp shuffle scan + warp-agg scan -> publish aggregate
//            -> decoupled lookback + 4-way fold -> per-thread start delta d
//            -> phase2: out_j = smemY_j + R[j]*d   (pure ILP, no rerun).

#define LSTEP 16
#define BLK 1024
#define MAXB 256

__device__ float g_fPhi[16];
__device__ float g_fGam[8];
__device__ float g_fM[18][16];        // M[s] = Phi^(LSTEP * 2^s)
__device__ float g_fR[LSTEP][8];      // rows 0 and 2 of Phi^(j+1)
__device__ float4 g_agg[MAXB];
__device__ int g_flag[MAXB];

__global__ void k_init(const float* c, const float* m, const float* k,
                       const float* dtp) {
    __shared__ double sA[16], sP[16], sT[16], sR[16], sPhiD[16], sQ[16];
    int t = threadIdx.x;           // 16 threads
    int r = t >> 2, col = t & 3;

    for (int i = t; i < MAXB; i += 16) g_flag[i] = 0;

    double c1 = c[0], c2 = c[1], c3 = c[2];
    double m1 = m[0], m2 = m[1];
    double k1 = k[0], k2 = k[1], k3 = k[2];
    double h = dtp[0];

    if (t == 0) {
        sA[0] = 0.0;  sA[1] = 1.0;  sA[2] = 0.0;  sA[3] = 0.0;
        sA[4] = -(k1 + k2) / m1; sA[5] = -(c1 + c2) / m1; sA[6] = k2 / m1; sA[7] = c2 / m1;
        sA[8] = 0.0;  sA[9] = 0.0;  sA[10] = 0.0; sA[11] = 1.0;
        sA[12] = k2 / m2; sA[13] = c2 / m2; sA[14] = -(k3 + k2) / m2; sA[15] = -(c3 + c2) / m2;
    }
    __syncwarp(0xffffu);

    double id = (r == col) ? 1.0 : 0.0;
    double h2 = h * h, h3 = h2 * h, h4 = h3 * h;
    double ph = id + h * sA[t];                 // Phi accumulator
    double g4 = h * id + (h2 / 2.0) * sA[t];    // G4 accumulator
    sP[t] = sA[t];
    __syncwarp(0xffffu);

    double coefP[3] = { h2 / 2.0, h3 / 6.0, h4 / 24.0 };
    double coefG[2] = { h3 / 6.0, h4 / 24.0 };
    for (int q = 0; q < 3; q++) {               // A^2, A^3, A^4
        double s = 0.0;
        for (int kk = 0; kk < 4; kk++) s += sP[r * 4 + kk] * sA[kk * 4 + col];
        __syncwarp(0xffffu);
        sP[t] = s;
        __syncwarp(0xffffu);
        ph += coefP[q] * s;
        if (q < 2) g4 += coefG[q] * s;
    }

    g_fPhi[t] = (float)ph;
    sT[t] = g4;
    sPhiD[t] = ph;
    __syncwarp(0xffffu);
    if (t < 8) {   // Gam = G4 * B with B[1][0]=1/m1, B[3][1]=1/m2
        int rr = t >> 1, cc = t & 1;
        g_fGam[t] = (float)(sT[rr * 4 + (cc ? 3 : 1)] / (cc ? m2 : m1));
    }
    __syncwarp(0xffffu);

    // R[j] = rows 0,2 of Phi^(j+1):  Q = Phi; loop j: emit rows, Q = Q*Phi
    sQ[t] = ph;
    __syncwarp(0xffffu);
    for (int j = 0; j < LSTEP; j++) {
        if (r == 0) g_fR[j][col] = (float)sQ[t];
        if (r == 2) g_fR[j][4 + col] = (float)sQ[t];
        double s = 0.0;
        for (int kk = 0; kk < 4; kk++) s += sQ[r * 4 + kk] * sPhiD[kk * 4 + col];
        __syncwarp(0xffffu);
        sQ[t] = s;
        __syncwarp(0xffffu);
    }

    // sR = Phi^LSTEP (LSTEP=16 -> 4 squarings of Phi)
    sR[t] = ph;
    __syncwarp(0xffffu);
    for (int q = 0; q < 4; q++) {
        double s = 0.0;
        for (int kk = 0; kk < 4; kk++) s += sR[r * 4 + kk] * sR[kk * 4 + col];
        __syncwarp(0xffffu);
        sR[t] = s;
        __syncwarp(0xffffu);
    }
    g_fM[0][t] = (float)sR[t];
    for (int ms = 1; ms < 18; ms++) {           // successive squarings
        double s = 0.0;
        for (int kk = 0; kk < 4; kk++) s += sR[r * 4 + kk] * sR[kk * 4 + col];
        __syncwarp(0xffffu);
        sR[t] = s;
        __syncwarp(0xffffu);
        g_fM[ms][t] = (float)sR[t];
    }
}

#define STEP(ua, ub)                                                                         \
    do {                                                                                     \
        float n0 = fmaf(P[3],  x3, fmaf(P[2],  x2, fmaf(P[1],  x1, fmaf(P[0],  x0,          \
                   fmaf(G[1], (ub), G[0] * (ua))))));                                        \
        float n1 = fmaf(P[7],  x3, fmaf(P[6],  x2, fmaf(P[5],  x1, fmaf(P[4],  x0,          \
                   fmaf(G[3], (ub), G[2] * (ua))))));                                        \
        float n2 = fmaf(P[11], x3, fmaf(P[10], x2, fmaf(P[9],  x1, fmaf(P[8],  x0,          \
                   fmaf(G[5], (ub), G[4] * (ua))))));                                        \
        float n3 = fmaf(P[15], x3, fmaf(P[14], x2, fmaf(P[13], x1, fmaf(P[12], x0,          \
                   fmaf(G[7], (ub), G[6] * (ua))))));                                        \
        x0 = n0; x1 = n1; x2 = n2; x3 = n3;                                                  \
    } while (0)

// _v = M*_w + _v
#define AFF(Mm, _v, _w)                                                                      \
    do {                                                                                     \
        float n0 = fmaf(Mm[0],  (_w).x, fmaf(Mm[1],  (_w).y, fmaf(Mm[2],  (_w).z, fmaf(Mm[3],  (_w).w, (_v).x)))); \
        float n1 = fmaf(Mm[4],  (_w).x, fmaf(Mm[5],  (_w).y, fmaf(Mm[6],  (_w).z, fmaf(Mm[7],  (_w).w, (_v).y)))); \
        float n2 = fmaf(Mm[8],  (_w).x, fmaf(Mm[9],  (_w).y, fmaf(Mm[10], (_w).z, fmaf(Mm[11], (_w).w, (_v).z)))); \
        float n3 = fmaf(Mm[12], (_w).x, fmaf(Mm[13], (_w).y, fmaf(Mm[14], (_w).z, fmaf(Mm[15], (_w).w, (_v).w)))); \
        (_v).x = n0; (_v).y = n1; (_v).z = n2; (_v).w = n3;                                  \
    } while (0)

// _w = M*_w
#define MATP(Mm, _w)                                                                         \
    do {                                                                                     \
        float n0 = fmaf(Mm[0],  (_w).x, fmaf(Mm[1],  (_w).y, fmaf(Mm[2],  (_w).z, Mm[3]  * (_w).w))); \
        float n1 = fmaf(Mm[4],  (_w).x, fmaf(Mm[5],  (_w).y, fmaf(Mm[6],  (_w).z, Mm[7]  * (_w).w))); \
        float n2 = fmaf(Mm[8],  (_w).x, fmaf(Mm[9],  (_w).y, fmaf(Mm[10], (_w).z, Mm[11] * (_w).w))); \
        float n3 = fmaf(Mm[12], (_w).x, fmaf(Mm[13], (_w).y, fmaf(Mm[14], (_w).z, Mm[15] * (_w).w))); \
        (_w).x = n0; (_w).y = n1; (_w).z = n2; (_w).w = n3;                                  \
    } while (0)

#define SHFL_UP4(_d, _v, _w)                                                                 \
    do {                                                                                     \
        (_w).x = __shfl_up_sync(0xffffffffu, (_v).x, (_d));                                  \
        (_w).y = __shfl_up_sync(0xffffffffu, (_v).y, (_d));                                  \
        (_w).z = __shfl_up_sync(0xffffffffu, (_v).z, (_d));                                  \
        (_w).w = __shfl_up_sync(0xffffffffu, (_v).w, (_d));                                  \
    } while (0)

extern __shared__ float2 sY[];                   // [LSTEP][BLK] per-step (z1,z2) from zero

__global__ void __launch_bounds__(BLK) k_main(const float* __restrict__ u,
                                              const float* __restrict__ x0in,
                                              float* __restrict__ out, int T) {
    __shared__ float sM[18][16];
    __shared__ float sR2[LSTEP][8];
    __shared__ float4 sWagg[32];
    __shared__ float4 sWscan[32];
    __shared__ float4 sAgg[MAXB];
    __shared__ float4 sF[4];
    __shared__ int sLen[4];
    __shared__ float4 sPref;

    int tid = threadIdx.x;
    int lane = tid & 31, wrp = tid >> 5;
    int b = blockIdx.x;
    int p = b * BLK + tid;

    if (tid < 288) ((float*)sM)[tid] = ((const float*)g_fM)[tid];
    else if (tid >= 512 && tid < 512 + 8 * LSTEP)
        ((float*)sR2)[tid - 512] = ((const float*)g_fR)[tid - 512];

    float P[16], G[8];
#pragma unroll
    for (int i = 0; i < 16; i++) P[i] = g_fPhi[i];
#pragma unroll
    for (int i = 0; i < 8; i++) G[i] = g_fGam[i];
    __syncthreads();                               // sM, sR2 ready

    int t0 = p * LSTEP;
    int te = t0 + LSTEP; if (te > T) te = T;
    int rem = te - t0; if (rem < 0) rem = 0;       // steps this thread owns (0..16)

    const float4* u4 = (const float4*)(u + 2 * t0);

    // ---- phase 1: STEP chain from 0 (chain 0 from x0), stash (z1,z2) in smem ----
    float x0 = 0.f, x1 = 0.f, x2 = 0.f, x3 = 0.f;
    if (p == 0) { x0 = x0in[0]; x1 = x0in[1]; x2 = x0in[2]; x3 = x0in[3]; }
    if (rem == LSTEP) {
#pragma unroll
        for (int j = 0; j < LSTEP / 2; j++) {
            float4 a = u4[j];
            STEP(a.x, a.y);
            sY[(2 * j) * BLK + tid] = make_float2(x0, x2);
            STEP(a.z, a.w);
            sY[(2 * j + 1) * BLK + tid] = make_float2(x0, x2);
        }
    } else if (rem > 0) {
        int j = 0;
        for (; 2 * (j + 1) <= rem; j++) {
            float4 a = u4[j];
            STEP(a.x, a.y); STEP(a.z, a.w);
        }
        if (2 * j < rem) {
            float2 hh = *(const float2*)(u + 2 * (t0 + 2 * j));
            STEP(hh.x, hh.y);
        }
    }
    float4 v = make_float4(x0, x1, x2, x3);

    // ---- warp Kogge-Stone scan (shuffles; M[0..4]) ----
#pragma unroll
    for (int s = 0; s < 5; s++) {
        int d = 1 << s;
        float4 w;
        SHFL_UP4(d, v, w);
        if (lane >= d) { const float* M = sM[s]; AFF(M, v, w); }
    }
    float4 ev;                                     // exclusive within-warp scan
    SHFL_UP4(1, v, ev);
    if (lane == 0) ev = make_float4(0.f, 0.f, 0.f, 0.f);
    if (lane == 31) sWagg[wrp] = v;
    __syncthreads();

    // ---- warp 0 scans the 32 warp aggregates (M[5..9]) ----
    if (wrp == 0) {
        float4 av = sWagg[lane];
#pragma unroll
        for (int s = 0; s < 5; s++) {
            int d = 1 << s;
            float4 w;
            SHFL_UP4(d, av, w);
            if (lane >= d) { const float* M = sM[5 + s]; AFF(M, av, w); }
        }
        sWscan[lane] = av;
    }
    __syncthreads();

    // ---- publish block aggregate ----
    if (tid == 0) {
        g_agg[b] = sWscan[31];
        __threadfence();
        atomicExch(&g_flag[b], 1);
    }

    // ---- decoupled lookback: wait for + load previous aggregates ----
    if (tid < b) {
        while (atomicAdd(&g_flag[tid], 0) == 0) { }
        __threadfence();
        sAgg[tid] = g_agg[tid];
    }
    __syncthreads();

    // ---- 4-way parallel fold: Pref_b = sum_{j<b} MB^{b-1-j} S_j, MB = M[10] ----
    const float* MB = sM[10];
    if (tid < 4) {
        int q = (b + 3) >> 2;
        int j0 = tid * q, j1 = j0 + q; if (j1 > b) j1 = b; if (j0 > b) j0 = b;
        float4 F = make_float4(0.f, 0.f, 0.f, 0.f);
        for (int j = j0; j < j1; j++) {
            float4 S = sAgg[j];
            MATP(MB, F);
            F.x += S.x; F.y += S.y; F.z += S.z; F.w += S.w;
        }
        sF[tid] = F; sLen[tid] = j1 - j0;
    }
    __syncthreads();
    if (tid == 0) {
        float4 acc = (b > 0) ? sF[0] : make_float4(0.f, 0.f, 0.f, 0.f);
#pragma unroll
        for (int l = 1; l < 4; l++) {
            int r = sLen[l];
#pragma unroll
            for (int s = 0; s < 7; s++)
                if ((r >> s) & 1) { const float* M = sM[10 + s]; MATP(M, acc); }
            float4 F = sF[l];
            acc.x += F.x; acc.y += F.y; acc.z += F.z; acc.w += F.w;
        }
        sPref = acc;
    }
    __syncthreads();

    if (t0 >= T) return;   // all barriers done; idle tail threads exit

    // ---- per-thread start delta d (d = x_start - phase1 start; 0 for p==0) ----
    float4 d4 = make_float4(0.f, 0.f, 0.f, 0.f);
    if (p != 0) {
        if (b > 0) {
            d4 = sPref;
#pragma unroll
            for (int s = 0; s < 10; s++)
                if ((tid >> s) & 1) { const float* M = sM[s]; MATP(M, d4); }
        }
        if (wrp > 0) {
            float4 wp = sWscan[wrp - 1];
#pragma unroll
            for (int s = 0; s < 5; s++)
                if ((lane >> s) & 1) { const float* M = sM[s]; MATP(M, wp); }
            d4.x += wp.x; d4.y += wp.y; d4.z += wp.z; d4.w += wp.w;
        }
        d4.x += ev.x; d4.y += ev.y; d4.z += ev.z; d4.w += ev.w;
    }

    // ---- phase 2: out_j = smemY_j + R[j] * d   (no serial chain, no u re-read) ----
    if (rem == LSTEP) {
        float4* o4 = (float4*)(out + 2 * t0);
#pragma unroll
        for (int j = 0; j < LSTEP / 2; j++) {
            float2 ya = sY[(2 * j) * BLK + tid];
            float2 yb = sY[(2 * j + 1) * BLK + tid];
            const float* Ra = sR2[2 * j];
            const float* Rb = sR2[2 * j + 1];
            float z1a = fmaf(Ra[0], d4.x, fmaf(Ra[1], d4.y, fmaf(Ra[2], d4.z, fmaf(Ra[3], d4.w, ya.x))));
            float z2a = fmaf(Ra[4], d4.x, fmaf(Ra[5], d4.y, fmaf(Ra[6], d4.z, fmaf(Ra[7], d4.w, ya.y))));
            float z1b = fmaf(Rb[0], d4.x, fmaf(Rb[1], d4.y, fmaf(Rb[2], d4.z, fmaf(Rb[3], d4.w, yb.x))));
            float z2b = fmaf(Rb[4], d4.x, fmaf(Rb[5], d4.y, fmaf(Rb[6], d4.z, fmaf(Rb[7], d4.w, yb.y))));
            o4[j] = make_float4(z1a, z2a, z1b, z2b);
        }
    } else {
        // tail: re-run STEP chain from the true start (rare path)
        if (p == 0) { x0 = x0in[0]; x1 = x0in[1]; x2 = x0in[2]; x3 = x0in[3]; }
        else        { x0 = d4.x; x1 = d4.y; x2 = d4.z; x3 = d4.w; }
        int j = 0;
        for (; 2 * (j + 1) <= rem; j++) {
            float4 a = u4[j];
            STEP(a.x, a.y); float p0 = x0, q0 = x2;
            STEP(a.z, a.w);
            *(float4*)(out + 2 * (t0 + 2 * j)) = make_float4(p0, q0, x0, x2);
        }
        if (2 * j < rem) {
            float2 hh = *(const float2*)(u + 2 * (t0 + 2 * j));
            STEP(hh.x, hh.y);
            *(float2*)(out + 2 * (t0 + 2 * j)) = make_float2(x0, x2);
        }
    }
}

extern "C" void kernel_launch(void* const* d_in, const int* in_sizes, int n_in,
                              void* d_out, int out_size) {
    const float* u  = (const float*)d_in[0];
    const float* x0 = (const float*)d_in[1];
    const float* c  = (const float*)d_in[2];
    const float* m  = (const float*)d_in[3];
    const float* k  = (const float*)d_in[4];
    const float* dt = (const float*)d_in[5];
    float* out = (float*)d_out;

    int T = in_sizes[0] / 2;
    int chains = (T + LSTEP - 1) / LSTEP;
    int grid = (chains + BLK - 1) / BLK;     // 123 for T = 2e6 -> single wave

    size_t dynSmem = (size_t)LSTEP * BLK * sizeof(float2);   // 128 KB
    cudaFuncSetAttribute(k_main, cudaFuncAttributeMaxDynamicSharedMemorySize,
                         (int)dynSmem);

    k_init<<<1, 16>>>(c, m, k, dt);
    k_main<<<grid, BLK, dynSmem>>>(u, x0, out, T);
}

// round 12
// speedup vs baseline: 1.4699x; 1.4540x over previous
#include <cuda_runtime.h>
#include <cuda_bf16.h>

// Single-pass fused blocked-scan RK4 on a 4-state LTI system, single-wave grid.
// x_{t+1} = Phi x_t + Gam u_t (exact RK4 algebra for linear ODE + ZOH input).
//   k_init : 16-thread FLOAT build of Phi, Gam, M[s]=Phi^(16*2^s) s=0..17,
//            R[j] = rows 0,2 of Phi^(j+1); zero flags.  (~1us, was ~6 in double)
//   k_main : <=148 co-resident blocks, 16 steps/thread:
//            coalesced burst-load of block's u tile into smem (MLP 8)
//            -> phase1 STEP chain reading smem, overwriting slots with (z1,z2)
//            -> warp shuffle scan + warp-agg scan -> publish aggregate
//            -> decoupled lookback + 4-way fold -> per-thread start delta d
//            -> phase2: out_j = y_j + R[j]*d  (pure ILP).

#define LSTEP 16
#define BLK 1024
#define MAXB 256
#define SU_STRIDE (BLK + 1)          // float2 row stride (pad kills bank conflicts)

__device__ float g_fPhi[16];
__device__ float g_fGam[8];
__device__ float g_fM[18][16];        // M[s] = Phi^(LSTEP * 2^s)
__device__ float g_fR[LSTEP][8];      // rows 0 and 2 of Phi^(j+1)
__device__ float4 g_agg[MAXB];
__device__ int g_flag[MAXB];

__global__ void k_init(const float* c, const float* m, const float* k,
                       const float* dtp) {
    __shared__ float sA[16], sP[16], sT[16], sR[16], sPhiD[16], sQ[16];
    int t = threadIdx.x;           // 16 threads
    int r = t >> 2, col = t & 3;

    for (int i = t; i < MAXB; i += 16) g_flag[i] = 0;

    float c1 = c[0], c2 = c[1], c3 = c[2];
    float m1 = m[0], m2 = m[1];
    float k1 = k[0], k2 = k[1], k3 = k[2];
    float h = dtp[0];

    if (t == 0) {
        sA[0] = 0.f;  sA[1] = 1.f;  sA[2] = 0.f;  sA[3] = 0.f;
        sA[4] = -(k1 + k2) / m1; sA[5] = -(c1 + c2) / m1; sA[6] = k2 / m1; sA[7] = c2 / m1;
        sA[8] = 0.f;  sA[9] = 0.f;  sA[10] = 0.f; sA[11] = 1.f;
        sA[12] = k2 / m2; sA[13] = c2 / m2; sA[14] = -(k3 + k2) / m2; sA[15] = -(c3 + c2) / m2;
    }
    __syncwarp(0xffffu);

    float id = (r == col) ? 1.f : 0.f;
    float h2 = h * h, h3 = h2 * h, h4 = h3 * h;
    float ph = id + h * sA[t];                 // Phi accumulator
    float g4 = h * id + (h2 / 2.f) * sA[t];    // G4 accumulator
    sP[t] = sA[t];
    __syncwarp(0xffffu);

    float coefP[3] = { h2 / 2.f, h3 / 6.f, h4 / 24.f };
    float coefG[2] = { h3 / 6.f, h4 / 24.f };
    for (int q = 0; q < 3; q++) {               // A^2, A^3, A^4
        float s = 0.f;
        for (int kk = 0; kk < 4; kk++) s = fmaf(sP[r * 4 + kk], sA[kk * 4 + col], s);
        __syncwarp(0xffffu);
        sP[t] = s;
        __syncwarp(0xffffu);
        ph = fmaf(coefP[q], s, ph);
        if (q < 2) g4 = fmaf(coefG[q], s, g4);
    }

    g_fPhi[t] = ph;
    sT[t] = g4;
    sPhiD[t] = ph;
    __syncwarp(0xffffu);
    if (t < 8) {   // Gam = G4 * B with B[1][0]=1/m1, B[3][1]=1/m2
        int rr = t >> 1, cc = t & 1;
        g_fGam[t] = sT[rr * 4 + (cc ? 3 : 1)] / (cc ? m2 : m1);
    }
    __syncwarp(0xffffu);

    // R[j] = rows 0,2 of Phi^(j+1):  Q = Phi; loop j: emit rows, Q = Q*Phi
    sQ[t] = ph;
    __syncwarp(0xffffu);
    for (int j = 0; j < LSTEP; j++) {
        if (r == 0) g_fR[j][col] = sQ[t];
        if (r == 2) g_fR[j][4 + col] = sQ[t];
        float s = 0.f;
        for (int kk = 0; kk < 4; kk++) s = fmaf(sQ[r * 4 + kk], sPhiD[kk * 4 + col], s);
        __syncwarp(0xffffu);
        sQ[t] = s;
        __syncwarp(0xffffu);
    }

    // sR = Phi^LSTEP (LSTEP=16 -> 4 squarings of Phi)
    sR[t] = ph;
    __syncwarp(0xffffu);
    for (int q = 0; q < 4; q++) {
        float s = 0.f;
        for (int kk = 0; kk < 4; kk++) s = fmaf(sR[r * 4 + kk], sR[kk * 4 + col], s);
        __syncwarp(0xffffu);
        sR[t] = s;
        __syncwarp(0xffffu);
    }
    g_fM[0][t] = sR[t];
    for (int ms = 1; ms < 18; ms++) {           // successive squarings
        float s = 0.f;
        for (int kk = 0; kk < 4; kk++) s = fmaf(sR[r * 4 + kk], sR[kk * 4 + col], s);
        __syncwarp(0xffffu);
        sR[t] = s;
        __syncwarp(0xffffu);
        g_fM[ms][t] = sR[t];
    }
}

#define STEP(ua, ub)                                                                         \
    do {                                                                                     \
        float n0 = fmaf(P[3],  x3, fmaf(P[2],  x2, fmaf(P[1],  x1, fmaf(P[0],  x0,          \
                   fmaf(G[1], (ub), G[0] * (ua))))));                                        \
        float n1 = fmaf(P[7],  x3, fmaf(P[6],  x2, fmaf(P[5],  x1, fmaf(P[4],  x0,          \
                   fmaf(G[3], (ub), G[2] * (ua))))));                                        \
        float n2 = fmaf(P[11], x3, fmaf(P[10], x2, fmaf(P[9],  x1, fmaf(P[8],  x0,          \
                   fmaf(G[5], (ub), G[4] * (ua))))));                                        \
        float n3 = fmaf(P[15], x3, fmaf(P[14], x2, fmaf(P[13], x1, fmaf(P[12], x0,          \
                   fmaf(G[7], (ub), G[6] * (ua))))));                                        \
        x0 = n0; x1 = n1; x2 = n2; x3 = n3;                                                  \
    } while (0)

// _v = M*_w + _v
#define AFF(Mm, _v, _w)                                                                      \
    do {                                                                                     \
        float n0 = fmaf(Mm[0],  (_w).x, fmaf(Mm[1],  (_w).y, fmaf(Mm[2],  (_w).z, fmaf(Mm[3],  (_w).w, (_v).x)))); \
        float n1 = fmaf(Mm[4],  (_w).x, fmaf(Mm[5],  (_w).y, fmaf(Mm[6],  (_w).z, fmaf(Mm[7],  (_w).w, (_v).y)))); \
        float n2 = fmaf(Mm[8],  (_w).x, fmaf(Mm[9],  (_w).y, fmaf(Mm[10], (_w).z, fmaf(Mm[11], (_w).w, (_v).z)))); \
        float n3 = fmaf(Mm[12], (_w).x, fmaf(Mm[13], (_w).y, fmaf(Mm[14], (_w).z, fmaf(Mm[15], (_w).w, (_v).w)))); \
        (_v).x = n0; (_v).y = n1; (_v).z = n2; (_v).w = n3;                                  \
    } while (0)

// _w = M*_w
#define MATP(Mm, _w)                                                                         \
    do {                                                                                     \
        float n0 = fmaf(Mm[0],  (_w).x, fmaf(Mm[1],  (_w).y, fmaf(Mm[2],  (_w).z, Mm[3]  * (_w).w))); \
        float n1 = fmaf(Mm[4],  (_w).x, fmaf(Mm[5],  (_w).y, fmaf(Mm[6],  (_w).z, Mm[7]  * (_w).w))); \
        float n2 = fmaf(Mm[8],  (_w).x, fmaf(Mm[9],  (_w).y, fmaf(Mm[10], (_w).z, Mm[11] * (_w).w))); \
        float n3 = fmaf(Mm[12], (_w).x, fmaf(Mm[13], (_w).y, fmaf(Mm[14], (_w).z, Mm[15] * (_w).w))); \
        (_w).x = n0; (_w).y = n1; (_w).z = n2; (_w).w = n3;                                  \
    } while (0)

#define SHFL_UP4(_d, _v, _w)                                                                 \
    do {                                                                                     \
        (_w).x = __shfl_up_sync(0xffffffffu, (_v).x, (_d));                                  \
        (_w).y = __shfl_up_sync(0xffffffffu, (_v).y, (_d));                                  \
        (_w).z = __shfl_up_sync(0xffffffffu, (_v).z, (_d));                                  \
        (_w).w = __shfl_up_sync(0xffffffffu, (_v).w, (_d));                                  \
    } while (0)

extern __shared__ float2 sU[];   // [LSTEP][SU_STRIDE]: u tile, overwritten with (z1,z2)

__global__ void __launch_bounds__(BLK) k_main(const float* __restrict__ u,
                                              const float* __restrict__ x0in,
                                              float* __restrict__ out, int T) {
    __shared__ float sM[18][16];
    __shared__ float sR2[LSTEP][8];
    __shared__ float4 sWagg[32];
    __shared__ float4 sWscan[32];
    __shared__ float4 sAgg[MAXB];
    __shared__ float4 sF[4];
    __shared__ int sLen[4];
    __shared__ float4 sPref;

    int tid = threadIdx.x;
    int lane = tid & 31, wrp = tid >> 5;
    int b = blockIdx.x;
    int p = b * BLK + tid;

    if (tid < 288) ((float*)sM)[tid] = ((const float*)g_fM)[tid];
    else if (tid >= 512 && tid < 512 + 8 * LSTEP)
        ((float*)sR2)[tid - 512] = ((const float*)g_fR)[tid - 512];

    float P[16], G[8];
#pragma unroll
    for (int i = 0; i < 16; i++) P[i] = g_fPhi[i];
#pragma unroll
    for (int i = 0; i < 8; i++) G[i] = g_fGam[i];

    // ---- coalesced burst load of this block's u tile into smem (MLP 8) ----
    {
        const float4* ug = (const float4*)u;
        int base4 = b * (BLK * LSTEP / 2);        // 8192 float4 per block
        int uTot = 2 * T;                         // floats in u
#pragma unroll
        for (int cny = 0; cny < 8; cny++) {
            int f = cny * BLK + tid;              // 0..8191
            int gf = base4 + f;
            float4 a = make_float4(0.f, 0.f, 0.f, 0.f);
            if (4 * gf + 4 <= uTot) {
                a = ug[gf];
            } else if (4 * gf < uTot) {           // ragged boundary (T odd cases)
                const float* us = u + 4 * gf;
                int n = uTot - 4 * gf;
                a.x = us[0];
                if (n > 1) a.y = us[1];
                if (n > 2) a.z = us[2];
            }
            int owner = f >> 3;
            int row = 2 * (f & 7);
            sU[row * SU_STRIDE + owner] = make_float2(a.x, a.y);
            sU[(row + 1) * SU_STRIDE + owner] = make_float2(a.z, a.w);
        }
    }
    __syncthreads();                              // sM, sR2, sU ready

    int t0 = p * LSTEP;
    int te = t0 + LSTEP; if (te > T) te = T;
    int rem = te - t0; if (rem < 0) rem = 0;      // steps this thread owns (0..16)

    // ---- phase 1: STEP chain from 0 (chain 0 from x0); overwrite slots with y ----
    float x0 = 0.f, x1 = 0.f, x2 = 0.f, x3 = 0.f;
    if (p == 0) { x0 = x0in[0]; x1 = x0in[1]; x2 = x0in[2]; x3 = x0in[3]; }
    if (rem == LSTEP) {
#pragma unroll
        for (int j = 0; j < LSTEP; j++) {
            float2 uu = sU[j * SU_STRIDE + tid];
            STEP(uu.x, uu.y);
            sU[j * SU_STRIDE + tid] = make_float2(x0, x2);
        }
    } else if (rem > 0) {
        for (int j = 0; j < rem; j++) {
            float2 uu = sU[j * SU_STRIDE + tid];
            STEP(uu.x, uu.y);
            sU[j * SU_STRIDE + tid] = make_float2(x0, x2);
        }
    }
    float4 v = make_float4(x0, x1, x2, x3);

    // ---- warp Kogge-Stone scan (shuffles; M[0..4]) ----
#pragma unroll
    for (int s = 0; s < 5; s++) {
        int d = 1 << s;
        float4 w;
        SHFL_UP4(d, v, w);
        if (lane >= d) { const float* M = sM[s]; AFF(M, v, w); }
    }
    float4 ev;                                     // exclusive within-warp scan
    SHFL_UP4(1, v, ev);
    if (lane == 0) ev = make_float4(0.f, 0.f, 0.f, 0.f);
    if (lane == 31) sWagg[wrp] = v;
    __syncthreads();

    // ---- warp 0 scans the 32 warp aggregates (M[5..9]) ----
    if (wrp == 0) {
        float4 av = sWagg[lane];
#pragma unroll
        for (int s = 0; s < 5; s++) {
            int d = 1 << s;
            float4 w;
            SHFL_UP4(d, av, w);
            if (lane >= d) { const float* M = sM[5 + s]; AFF(M, av, w); }
        }
        sWscan[lane] = av;
    }
    __syncthreads();

    // ---- publish block aggregate ----
    if (tid == 0) {
        g_agg[b] = sWscan[31];
        __threadfence();
        atomicExch(&g_flag[b], 1);
    }

    // ---- decoupled lookback: wait for + load previous aggregates ----
    if (tid < b) {
        while (atomicAdd(&g_flag[tid], 0) == 0) { }
        __threadfence();
        sAgg[tid] = g_agg[tid];
    }
    __syncthreads();

    // ---- 4-way parallel fold: Pref_b = sum_{j<b} MB^{b-1-j} S_j, MB = M[10] ----
    const float* MB = sM[10];
    if (tid < 4) {
        int q = (b + 3) >> 2;
        int j0 = tid * q, j1 = j0 + q; if (j1 > b) j1 = b; if (j0 > b) j0 = b;
        float4 F = make_float4(0.f, 0.f, 0.f, 0.f);
        for (int j = j0; j < j1; j++) {
            float4 S = sAgg[j];
            MATP(MB, F);
            F.x += S.x; F.y += S.y; F.z += S.z; F.w += S.w;
        }
        sF[tid] = F; sLen[tid] = j1 - j0;
    }
    __syncthreads();
    if (tid == 0) {
        float4 acc = (b > 0) ? sF[0] : make_float4(0.f, 0.f, 0.f, 0.f);
#pragma unroll
        for (int l = 1; l < 4; l++) {
            int r = sLen[l];
#pragma unroll
            for (int s = 0; s < 7; s++)
                if ((r >> s) & 1) { const float* M = sM[10 + s]; MATP(M, acc); }
            float4 F = sF[l];
            acc.x += F.x; acc.y += F.y; acc.z += F.z; acc.w += F.w;
        }
        sPref = acc;
    }
    __syncthreads();

    if (rem == 0) return;   // all barriers done; idle tail threads exit

    // ---- per-thread start delta d (d = x_start - phase1 start; 0 for p==0) ----
    float4 d4 = make_float4(0.f, 0.f, 0.f, 0.f);
    if (p != 0) {
        if (b > 0) {
            d4 = sPref;
#pragma unroll
            for (int s = 0; s < 10; s++)
                if ((tid >> s) & 1) { const float* M = sM[s]; MATP(M, d4); }
        }
        if (wrp > 0) {
            float4 wp = sWscan[wrp - 1];
#pragma unroll
            for (int s = 0; s < 5; s++)
                if ((lane >> s) & 1) { const float* M = sM[s]; MATP(M, wp); }
            d4.x += wp.x; d4.y += wp.y; d4.z += wp.z; d4.w += wp.w;
        }
        d4.x += ev.x; d4.y += ev.y; d4.z += ev.z; d4.w += ev.w;
    }

    // ---- phase 2: out_j = y_j + R[j] * d   (no serial chain, no u re-read) ----
    if (rem == LSTEP) {
        float4* o4 = (float4*)(out + 2 * t0);
#pragma unroll
        for (int j = 0; j < LSTEP / 2; j++) {
            float2 ya = sU[(2 * j) * SU_STRIDE + tid];
            float2 yb = sU[(2 * j + 1) * SU_STRIDE + tid];
            const float* Ra = sR2[2 * j];
            const float* Rb = sR2[2 * j + 1];
            float z1a = fmaf(Ra[0], d4.x, fmaf(Ra[1], d4.y, fmaf(Ra[2], d4.z, fmaf(Ra[3], d4.w, ya.x))));
            float z2a = fmaf(Ra[4], d4.x, fmaf(Ra[5], d4.y, fmaf(Ra[6], d4.z, fmaf(Ra[7], d4.w, ya.y))));
            float z1b = fmaf(Rb[0], d4.x, fmaf(Rb[1], d4.y, fmaf(Rb[2], d4.z, fmaf(Rb[3], d4.w, yb.x))));
            float z2b = fmaf(Rb[4], d4.x, fmaf(Rb[5], d4.y, fmaf(Rb[6], d4.z, fmaf(Rb[7], d4.w, yb.y))));
            o4[j] = make_float4(z1a, z2a, z1b, z2b);
        }
    } else {
        for (int j = 0; j < rem; j++) {
            float2 y = sU[j * SU_STRIDE + tid];
            const float* R = sR2[j];
            float z1 = fmaf(R[0], d4.x, fmaf(R[1], d4.y, fmaf(R[2], d4.z, fmaf(R[3], d4.w, y.x))));
            float z2 = fmaf(R[4], d4.x, fmaf(R[5], d4.y, fmaf(R[6], d4.z, fmaf(R[7], d4.w, y.y))));
            *(float2*)(out + 2 * (t0 + j)) = make_float2(z1, z2);
        }
    }
}

extern "C" void kernel_launch(void* const* d_in, const int* in_sizes, int n_in,
                              void* d_out, int out_size) {
    const float* u  = (const float*)d_in[0];
    const float* x0 = (const float*)d_in[1];
    const float* c  = (const float*)d_in[2];
    const float* m  = (const float*)d_in[3];
    const float* k  = (const float*)d_in[4];
    const float* dt = (const float*)d_in[5];
    float* out = (float*)d_out;

    int T = in_sizes[0] / 2;
    int chains = (T + LSTEP - 1) / LSTEP;
    int grid = (chains + BLK - 1) / BLK;     // 123 for T = 2e6 -> single wave

    size_t dynSmem = (size_t)LSTEP * SU_STRIDE * sizeof(float2);   // ~131 KB
    cudaFuncSetAttribute(k_main, cudaFuncAttributeMaxDynamicSharedMemorySize,
                         (int)dynSmem);

    k_init<<<1, 16>>>(c, m, k, dt);
    k_main<<<grid, BLK, dynSmem>>>(u, x0, out, T);
}

// round 14
// speedup vs baseline: 1.5146x; 1.0304x over previous
#include <cuda_runtime.h>
#include <cuda_bf16.h>

// Single-pass fused blocked-scan RK4 on a 4-state LTI system.
// x_{t+1} = Phi x_t + Gam u_t (exact RK4 algebra for linear ODE + ZOH input).
//   k_init : 16-thread float build of Phi, Gam, M[s]=Phi^(16*2^s) s=0..17,
//            R[j] = rows 0,2 of Phi^(j+1); zero flags.
//   k_main : BLK=512, 2 blocks/SM co-resident (65KB smem tile), 16 steps/thread:
//            burst-load u tile -> phase1 STEP chain (slots overwritten with y)
//            -> warp KS scan (M[0..4]) + warp-agg scan over 16 warps (M[5..8])
//            -> publish -> lookback + 4-way fold (MB=M[9], powers M[9+s])
//            -> per-thread delta (9-bit tid powers) -> phase2 affine correction.

#define LSTEP 16
#define BLK 512
#define NWARP (BLK / 32)
#define MAXB 512
#define SU_STRIDE (BLK + 1)          // float2 row stride (pad kills bank conflicts)

__device__ float g_fPhi[16];
__device__ float g_fGam[8];
__device__ float g_fM[18][16];        // M[s] = Phi^(LSTEP * 2^s)
__device__ float g_fR[LSTEP][8];      // rows 0 and 2 of Phi^(j+1)
__device__ float4 g_agg[MAXB];
__device__ int g_flag[MAXB];

__global__ void k_init(const float* c, const float* m, const float* k,
                       const float* dtp) {
    __shared__ float sA[16], sP[16], sT[16], sR[16], sPhiD[16], sQ[16];
    int t = threadIdx.x;           // 16 threads
    int r = t >> 2, col = t & 3;

    for (int i = t; i < MAXB; i += 16) g_flag[i] = 0;

    float c1 = c[0], c2 = c[1], c3 = c[2];
    float m1 = m[0], m2 = m[1];
    float k1 = k[0], k2 = k[1], k3 = k[2];
    float h = dtp[0];

    if (t == 0) {
        sA[0] = 0.f;  sA[1] = 1.f;  sA[2] = 0.f;  sA[3] = 0.f;
        sA[4] = -(k1 + k2) / m1; sA[5] = -(c1 + c2) / m1; sA[6] = k2 / m1; sA[7] = c2 / m1;
        sA[8] = 0.f;  sA[9] = 0.f;  sA[10] = 0.f; sA[11] = 1.f;
        sA[12] = k2 / m2; sA[13] = c2 / m2; sA[14] = -(k3 + k2) / m2; sA[15] = -(c3 + c2) / m2;
    }
    __syncwarp(0xffffu);

    float id = (r == col) ? 1.f : 0.f;
    float h2 = h * h, h3 = h2 * h, h4 = h3 * h;
    float ph = id + h * sA[t];                 // Phi accumulator
    float g4 = h * id + (h2 / 2.f) * sA[t];    // G4 accumulator
    sP[t] = sA[t];
    __syncwarp(0xffffu);

    float coefP[3] = { h2 / 2.f, h3 / 6.f, h4 / 24.f };
    float coefG[2] = { h3 / 6.f, h4 / 24.f };
    for (int q = 0; q < 3; q++) {               // A^2, A^3, A^4
        float s = 0.f;
        for (int kk = 0; kk < 4; kk++) s = fmaf(sP[r * 4 + kk], sA[kk * 4 + col], s);
        __syncwarp(0xffffu);
        sP[t] = s;
        __syncwarp(0xffffu);
        ph = fmaf(coefP[q], s, ph);
        if (q < 2) g4 = fmaf(coefG[q], s, g4);
    }

    g_fPhi[t] = ph;
    sT[t] = g4;
    sPhiD[t] = ph;
    __syncwarp(0xffffu);
    if (t < 8) {   // Gam = G4 * B with B[1][0]=1/m1, B[3][1]=1/m2
        int rr = t >> 1, cc = t & 1;
        g_fGam[t] = sT[rr * 4 + (cc ? 3 : 1)] / (cc ? m2 : m1);
    }
    __syncwarp(0xffffu);

    // R[j] = rows 0,2 of Phi^(j+1):  Q = Phi; loop j: emit rows, Q = Q*Phi
    sQ[t] = ph;
    __syncwarp(0xffffu);
    for (int j = 0; j < LSTEP; j++) {
        if (r == 0) g_fR[j][col] = sQ[t];
        if (r == 2) g_fR[j][4 + col] = sQ[t];
        float s = 0.f;
        for (int kk = 0; kk < 4; kk++) s = fmaf(sQ[r * 4 + kk], sPhiD[kk * 4 + col], s);
        __syncwarp(0xffffu);
        sQ[t] = s;
        __syncwarp(0xffffu);
    }

    // sR = Phi^LSTEP (LSTEP=16 -> 4 squarings of Phi)
    sR[t] = ph;
    __syncwarp(0xffffu);
    for (int q = 0; q < 4; q++) {
        float s = 0.f;
        for (int kk = 0; kk < 4; kk++) s = fmaf(sR[r * 4 + kk], sR[kk * 4 + col], s);
        __syncwarp(0xffffu);
        sR[t] = s;
        __syncwarp(0xffffu);
    }
    g_fM[0][t] = sR[t];
    for (int ms = 1; ms < 18; ms++) {           // successive squarings
        float s = 0.f;
        for (int kk = 0; kk < 4; kk++) s = fmaf(sR[r * 4 + kk], sR[kk * 4 + col], s);
        __syncwarp(0xffffu);
        sR[t] = s;
        __syncwarp(0xffffu);
        g_fM[ms][t] = sR[t];
    }
}

#define STEP(ua, ub)                                                                         \
    do {                                                                                     \
        float n0 = fmaf(P[3],  x3, fmaf(P[2],  x2, fmaf(P[1],  x1, fmaf(P[0],  x0,          \
                   fmaf(G[1], (ub), G[0] * (ua))))));                                        \
        float n1 = fmaf(P[7],  x3, fmaf(P[6],  x2, fmaf(P[5],  x1, fmaf(P[4],  x0,          \
                   fmaf(G[3], (ub), G[2] * (ua))))));                                        \
        float n2 = fmaf(P[11], x3, fmaf(P[10], x2, fmaf(P[9],  x1, fmaf(P[8],  x0,          \
                   fmaf(G[5], (ub), G[4] * (ua))))));                                        \
        float n3 = fmaf(P[15], x3, fmaf(P[14], x2, fmaf(P[13], x1, fmaf(P[12], x0,          \
                   fmaf(G[7], (ub), G[6] * (ua))))));                                        \
        x0 = n0; x1 = n1; x2 = n2; x3 = n3;                                                  \
    } while (0)

// _v = M*_w + _v
#define AFF(Mm, _v, _w)                                                                      \
    do {                                                                                     \
        float n0 = fmaf(Mm[0],  (_w).x, fmaf(Mm[1],  (_w).y, fmaf(Mm[2],  (_w).z, fmaf(Mm[3],  (_w).w, (_v).x)))); \
        float n1 = fmaf(Mm[4],  (_w).x, fmaf(Mm[5],  (_w).y, fmaf(Mm[6],  (_w).z, fmaf(Mm[7],  (_w).w, (_v).y)))); \
        float n2 = fmaf(Mm[8],  (_w).x, fmaf(Mm[9],  (_w).y, fmaf(Mm[10], (_w).z, fmaf(Mm[11], (_w).w, (_v).z)))); \
        float n3 = fmaf(Mm[12], (_w).x, fmaf(Mm[13], (_w).y, fmaf(Mm[14], (_w).z, fmaf(Mm[15], (_w).w, (_v).w)))); \
        (_v).x = n0; (_v).y = n1; (_v).z = n2; (_v).w = n3;                                  \
    } while (0)

// _w = M*_w
#define MATP(Mm, _w)                                                                         \
    do {                                                                                     \
        float n0 = fmaf(Mm[0],  (_w).x, fmaf(Mm[1],  (_w).y, fmaf(Mm[2],  (_w).z, Mm[3]  * (_w).w))); \
        float n1 = fmaf(Mm[4],  (_w).x, fmaf(Mm[5],  (_w).y, fmaf(Mm[6],  (_w).z, Mm[7]  * (_w).w))); \
        float n2 = fmaf(Mm[8],  (_w).x, fmaf(Mm[9],  (_w).y, fmaf(Mm[10], (_w).z, Mm[11] * (_w).w))); \
        float n3 = fmaf(Mm[12], (_w).x, fmaf(Mm[13], (_w).y, fmaf(Mm[14], (_w).z, Mm[15] * (_w).w))); \
        (_w).x = n0; (_w).y = n1; (_w).z = n2; (_w).w = n3;                                  \
    } while (0)

#define SHFL_UP4(_d, _v, _w)                                                                 \
    do {                                                                                     \
        (_w).x = __shfl_up_sync(0xffffffffu, (_v).x, (_d));                                  \
        (_w).y = __shfl_up_sync(0xffffffffu, (_v).y, (_d));                                  \
        (_w).z = __shfl_up_sync(0xffffffffu, (_v).z, (_d));                                  \
        (_w).w = __shfl_up_sync(0xffffffffu, (_v).w, (_d));                                  \
    } while (0)

extern __shared__ float2 sU[];   // [LSTEP][SU_STRIDE]: u tile, overwritten with (z1,z2)

__global__ void __launch_bounds__(BLK, 2) k_main(const float* __restrict__ u,
                                                 const float* __restrict__ x0in,
                                                 float* __restrict__ out, int T) {
    __shared__ float sM[18][16];
    __shared__ float sR2[LSTEP][8];
    __shared__ float4 sWagg[NWARP];
    __shared__ float4 sWscan[NWARP];
    __shared__ float4 sAgg[MAXB];
    __shared__ float4 sF[4];
    __shared__ int sLen[4];
    __shared__ float4 sPref;

    int tid = threadIdx.x;
    int lane = tid & 31, wrp = tid >> 5;
    int b = blockIdx.x;
    int p = b * BLK + tid;

    if (tid < 288) ((float*)sM)[tid] = ((const float*)g_fM)[tid];
    else if (tid >= 320 && tid < 320 + 8 * LSTEP)
        ((float*)sR2)[tid - 320] = ((const float*)g_fR)[tid - 320];

    float P[16], G[8];
#pragma unroll
    for (int i = 0; i < 16; i++) P[i] = g_fPhi[i];
#pragma unroll
    for (int i = 0; i < 8; i++) G[i] = g_fGam[i];

    // ---- coalesced burst load of this block's u tile into smem (MLP 8) ----
    {
        const float4* ug = (const float4*)u;
        int base4 = b * (BLK * LSTEP / 2);        // 4096 float4 per block
        int uTot = 2 * T;                         // floats in u
#pragma unroll
        for (int cny = 0; cny < 8; cny++) {
            int f = cny * BLK + tid;              // 0..4095
            int gf = base4 + f;
            float4 a = make_float4(0.f, 0.f, 0.f, 0.f);
            if (4 * gf + 4 <= uTot) {
                a = ug[gf];
            } else if (4 * gf < uTot) {           // ragged boundary
                const float* us = u + 4 * gf;
                int n = uTot - 4 * gf;
                a.x = us[0];
                if (n > 1) a.y = us[1];
                if (n > 2) a.z = us[2];
            }
            int owner = f >> 3;
            int row = 2 * (f & 7);
            sU[row * SU_STRIDE + owner] = make_float2(a.x, a.y);
            sU[(row + 1) * SU_STRIDE + owner] = make_float2(a.z, a.w);
        }
    }
    __syncthreads();                              // sM, sR2, sU ready

    int t0 = p * LSTEP;
    int te = t0 + LSTEP; if (te > T) te = T;
    int rem = te - t0; if (rem < 0) rem = 0;      // steps this thread owns (0..16)

    // ---- phase 1: STEP chain from 0 (chain 0 from x0); overwrite slots with y ----
    float x0 = 0.f, x1 = 0.f, x2 = 0.f, x3 = 0.f;
    if (p == 0) { x0 = x0in[0]; x1 = x0in[1]; x2 = x0in[2]; x3 = x0in[3]; }
    if (rem == LSTEP) {
#pragma unroll
        for (int j = 0; j < LSTEP; j++) {
            float2 uu = sU[j * SU_STRIDE + tid];
            STEP(uu.x, uu.y);
            sU[j * SU_STRIDE + tid] = make_float2(x0, x2);
        }
    } else if (rem > 0) {
        for (int j = 0; j < rem; j++) {
            float2 uu = sU[j * SU_STRIDE + tid];
            STEP(uu.x, uu.y);
            sU[j * SU_STRIDE + tid] = make_float2(x0, x2);
        }
    }
    float4 v = make_float4(x0, x1, x2, x3);

    // ---- warp Kogge-Stone scan (shuffles; M[0..4]) ----
#pragma unroll
    for (int s = 0; s < 5; s++) {
        int d = 1 << s;
        float4 w;
        SHFL_UP4(d, v, w);
        if (lane >= d) { const float* M = sM[s]; AFF(M, v, w); }
    }
    float4 ev;                                     // exclusive within-warp scan
    SHFL_UP4(1, v, ev);
    if (lane == 0) ev = make_float4(0.f, 0.f, 0.f, 0.f);
    if (lane == 31) sWagg[wrp] = v;
    __syncthreads();

    // ---- warp 0 scans the NWARP=16 warp aggregates (M[5..8]) ----
    // ALL 32 lanes execute the shuffles (full-mask safety); lanes >= NWARP
    // work on a clamped dummy value and never write.
    if (wrp == 0) {
        float4 av = sWagg[lane < NWARP ? lane : (NWARP - 1)];
#pragma unroll
        for (int s = 0; s < 4; s++) {
            int d = 1 << s;
            float4 w;
            SHFL_UP4(d, av, w);
            if (lane >= d && lane < NWARP) { const float* M = sM[5 + s]; AFF(M, av, w); }
        }
        if (lane < NWARP) sWscan[lane] = av;
    }
    __syncthreads();

    // ---- publish block aggregate ----
    if (tid == 0) {
        g_agg[b] = sWscan[NWARP - 1];
        __threadfence();
        atomicExch(&g_flag[b], 1);
    }

    // ---- decoupled lookback: wait for + load previous aggregates ----
    if (tid < b) {
        while (atomicAdd(&g_flag[tid], 0) == 0) { }
        __threadfence();
        sAgg[tid] = g_agg[tid];
    }
    __syncthreads();

    // ---- 4-way parallel fold: Pref_b = sum_{j<b} MB^{b-1-j} S_j, MB = M[9] ----
    const float* MB = sM[9];
    if (tid < 4) {
        int q = (b + 3) >> 2;
        int j0 = tid * q, j1 = j0 + q; if (j1 > b) j1 = b; if (j0 > b) j0 = b;
        float4 F = make_float4(0.f, 0.f, 0.f, 0.f);
        for (int j = j0; j < j1; j++) {
            float4 S = sAgg[j];
            MATP(MB, F);
            F.x += S.x; F.y += S.y; F.z += S.z; F.w += S.w;
        }
        sF[tid] = F; sLen[tid] = j1 - j0;
    }
    __syncthreads();
    if (tid == 0) {
        float4 acc = (b > 0) ? sF[0] : make_float4(0.f, 0.f, 0.f, 0.f);
#pragma unroll
        for (int l = 1; l < 4; l++) {
            int r = sLen[l];
#pragma unroll
            for (int s = 0; s < 7; s++)
                if ((r >> s) & 1) { const float* M = sM[9 + s]; MATP(M, acc); }
            float4 F = sF[l];
            acc.x += F.x; acc.y += F.y; acc.z += F.z; acc.w += F.w;
        }
        sPref = acc;
    }
    __syncthreads();

    if (rem == 0) return;   // all barriers done; idle tail threads exit

    // ---- per-thread start delta d (d = x_start - phase1 start; 0 for p==0) ----
    float4 d4 = make_float4(0.f, 0.f, 0.f, 0.f);
    if (p != 0) {
        if (b > 0) {
            d4 = sPref;
#pragma unroll
            for (int s = 0; s < 9; s++)                 // tid < 512 -> 9 bits
                if ((tid >> s) & 1) { const float* M = sM[s]; MATP(M, d4); }
        }
        if (wrp > 0) {
            float4 wp = sWscan[wrp - 1];
#pragma unroll
            for (int s = 0; s < 5; s++)
                if ((lane >> s) & 1) { const float* M = sM[s]; MATP(M, wp); }
            d4.x += wp.x; d4.y += wp.y; d4.z += wp.z; d4.w += wp.w;
        }
        d4.x += ev.x; d4.y += ev.y; d4.z += ev.z; d4.w += ev.w;
    }

    // ---- phase 2: out_j = y_j + R[j] * d   (no serial chain, no u re-read) ----
    if (rem == LSTEP) {
        float4* o4 = (float4*)(out + 2 * t0);
#pragma unroll
        for (int j = 0; j < LSTEP / 2; j++) {
            float2 ya = sU[(2 * j) * SU_STRIDE + tid];
            float2 yb = sU[(2 * j + 1) * SU_STRIDE + tid];
            const float* Ra = sR2[2 * j];
            const float* Rb = sR2[2 * j + 1];
            float z1a = fmaf(Ra[0], d4.x, fmaf(Ra[1], d4.y, fmaf(Ra[2], d4.z, fmaf(Ra[3], d4.w, ya.x))));
            float z2a = fmaf(Ra[4], d4.x, fmaf(Ra[5], d4.y, fmaf(Ra[6], d4.z, fmaf(Ra[7], d4.w, ya.y))));
            float z1b = fmaf(Rb[0], d4.x, fmaf(Rb[1], d4.y, fmaf(Rb[2], d4.z, fmaf(Rb[3], d4.w, yb.x))));
            float z2b = fmaf(Rb[4], d4.x, fmaf(Rb[5], d4.y, fmaf(Rb[6], d4.z, fmaf(Rb[7], d4.w, yb.y))));
            o4[j] = make_float4(z1a, z2a, z1b, z2b);
        }
    } else {
        for (int j = 0; j < rem; j++) {
            float2 y = sU[j * SU_STRIDE + tid];
            const float* R = sR2[j];
            float z1 = fmaf(R[0], d4.x, fmaf(R[1], d4.y, fmaf(R[2], d4.z, fmaf(R[3], d4.w, y.x))));
            float z2 = fmaf(R[4], d4.x, fmaf(R[5], d4.y, fmaf(R[6], d4.z, fmaf(R[7], d4.w, y.y))));
            *(float2*)(out + 2 * (t0 + j)) = make_float2(z1, z2);
        }
    }
}

extern "C" void kernel_launch(void* const* d_in, const int* in_sizes, int n_in,
                              void* d_out, int out_size) {
    const float* u  = (const float*)d_in[0];
    const float* x0 = (const float*)d_in[1];
    const float* c  = (const float*)d_in[2];
    const float* m  = (const float*)d_in[3];
    const float* k  = (const float*)d_in[4];
    const float* dt = (const float*)d_in[5];
    float* out = (float*)d_out;

    int T = in_sizes[0] / 2;
    int chains = (T + LSTEP - 1) / LSTEP;
    int grid = (chains + BLK - 1) / BLK;     // 245 for T = 2e6; 2/SM -> single wave

    size_t dynSmem = (size_t)LSTEP * SU_STRIDE * sizeof(float2);   // ~65.7 KB
    cudaFuncSetAttribute(k_main, cudaFuncAttributeMaxDynamicSharedMemorySize,
                         (int)dynSmem);

    k_init<<<1, 16>>>(c, m, k, dt);
    k_main<<<grid, BLK, dynSmem>>>(u, x0, out, T);
}